// round 7
// baseline (speedup 1.0000x reference)
#include <cuda_runtime.h>

// GATv2 2-layer forward.
// x[2,1024,128], adj[2,1024,1024] i32, W1[64,128], a1[8], W2[8,64], a2[8]
// out[2,1024,8] f32
//
// Score identity: leaky(s) = 0.6*s + 0.4*|s|  =>
//   log2e*e(i,j,h) = C[i,h] + C[j,h] + sum_f (0.4*log2e*a_f)*|g_i,f + g_j,f|
// with C = 0.6*log2e*(a . g) computed in the GEMM epilogue (8-lane shfl).
// Max-free softmax (scores O(1); partials sum linearly).
// Adjacency packed to bitmask once (ballot).

#define LOG2E 1.4426950408889634f
typedef unsigned long long u64;

__device__ __forceinline__ float fexp2(float x) {
    float y;
    asm("ex2.approx.ftz.f32 %0, %1;" : "=f"(y) : "f"(x));
    return y;
}
__device__ __forceinline__ u64 add2(u64 a, u64 b) {
    u64 o; asm("add.rn.f32x2 %0,%1,%2;" : "=l"(o) : "l"(a), "l"(b)); return o;
}
__device__ __forceinline__ u64 mul2(u64 a, u64 b) {
    u64 o; asm("mul.rn.f32x2 %0,%1,%2;" : "=l"(o) : "l"(a), "l"(b)); return o;
}
__device__ __forceinline__ u64 fma2(u64 a, u64 b, u64 c) {
    u64 o; asm("fma.rn.f32x2 %0,%1,%2,%3;" : "=l"(o) : "l"(a), "l"(b), "l"(c)); return o;
}
__device__ __forceinline__ u64 pack2(float lo, float hi) {
    u64 o; asm("mov.b64 %0,{%1,%2};" : "=l"(o) : "f"(lo), "f"(hi)); return o;
}
__device__ __forceinline__ float2 unpack2(u64 a) {
    float2 r; asm("mov.b64 {%0,%1},%2;" : "=f"(r.x), "=f"(r.y) : "l"(a)); return r;
}

// scratch (allocation-free rule: __device__ globals)
__device__ float d_g1[2 * 1024 * 64];
__device__ float d_h1[2 * 1024 * 64];
__device__ float d_g2[2 * 1024 * 8];
__device__ float d_c1[2 * 1024 * 8];
__device__ float d_c2[2 * 1024];
__device__ unsigned d_bits[2 * 1024 * 32];

// ---------------------------------------------------------------------------
__global__ __launch_bounds__(256) void adj2bits(const int* __restrict__ adj,
                                                unsigned* __restrict__ bits) {
    int gw = (blockIdx.x * 256 + threadIdx.x) >> 5;
    int lane = threadIdx.x & 31;
    int v[8];
    size_t base = (size_t)gw * 8 * 32 + lane;
#pragma unroll
    for (int k = 0; k < 8; k++) v[k] = adj[base + k * 32];
#pragma unroll
    for (int k = 0; k < 8; k++) {
        unsigned m = __ballot_sync(0xffffffffu, v[k] != 0);
        if (lane == 0) bits[gw * 8 + k] = m;
    }
}

// ---------------------------------------------------------------------------
// small GEMM: out[M,K] = X[M,D] @ W[K,D]^T, fused C epilogue:
// C[r, c>>3] = 0.6*log2e * sum_f A[f] * out[r, (c&~7)+f]  (8-lane shfl reduce;
// lanes of one head are contiguous and f-aligned since K % 8 == 0).
// ---------------------------------------------------------------------------
template <int D, int K, int RPB>
__global__ __launch_bounds__(K* RPB) void gemm_nt(const float* __restrict__ X,
                                                  const float* __restrict__ W,
                                                  const float* __restrict__ A,
                                                  float* __restrict__ out,
                                                  float* __restrict__ C, int M) {
    __shared__ float wsh[D * (K + 1)];
    for (int idx = threadIdx.x; idx < D * K; idx += blockDim.x) {
        int c = idx / D, d = idx % D;
        wsh[d * (K + 1) + c] = W[idx];
    }
    __syncthreads();
    int c = threadIdx.x % K;
    int r = blockIdx.x * RPB + threadIdx.x / K;
    const float4* x4 = (const float4*)(X + (size_t)r * D);
    float acc = 0.f;
#pragma unroll
    for (int d4 = 0; d4 < D / 4; d4++) {
        float4 xv = __ldg(x4 + d4);
        acc = fmaf(xv.x, wsh[(d4 * 4 + 0) * (K + 1) + c], acc);
        acc = fmaf(xv.y, wsh[(d4 * 4 + 1) * (K + 1) + c], acc);
        acc = fmaf(xv.z, wsh[(d4 * 4 + 2) * (K + 1) + c], acc);
        acc = fmaf(xv.w, wsh[(d4 * 4 + 3) * (K + 1) + c], acc);
    }
    out[(size_t)r * K + c] = acc;
    // fused C epilogue
    float t = acc * __ldg(A + (c & 7));
    t += __shfl_xor_sync(0xffffffffu, t, 1);
    t += __shfl_xor_sync(0xffffffffu, t, 2);
    t += __shfl_xor_sync(0xffffffffu, t, 4);
    if ((c & 7) == 0) C[(size_t)r * (K / 8) + (c >> 3)] = 0.6f * LOG2E * t;
}

// ---------------------------------------------------------------------------
// attn layer 1: H=8, F=8. CTA = 256 thr = 8 warps = 2 rows x 4 j-splits;
// ONE row per warp (small reg state), TWO independent j-chains per lane
// (strips k and k+4) for 2x memory/score ILP; accumulators shared.
// lane = jg*8 + h. g tile stride 12/head (conflict-free LDS.128); C separate,
// stride 8 (conflict-free LDS.32). Staging q-permuted (conflict-free STS.128).
// ---------------------------------------------------------------------------
__global__ __launch_bounds__(256, 3) void attn1_kernel(
    const float* __restrict__ G, const unsigned* __restrict__ BITS,
    const float* __restrict__ C, const float* __restrict__ AW,
    float* __restrict__ OUT, int N) {
    constexpr int S = 96;   // 8 heads * 12-word stride
    constexpr int TJ = 128;

    extern __shared__ float smem[];
    float* gsh = smem;                 // TJ*S
    float* csh = smem + TJ * S;        // TJ*8
    float* psum = csh + TJ * 8;        // 8 warps * 8 h * 9

    int tid = threadIdx.x;
    int w = tid >> 5, lane = tid & 31;
    int r = w & 1, sp = w >> 1;        // row, split
    int h = lane & 7, jg = lane >> 3;
    int base = sp * 4 + jg;            // [0,16)

    int iflat = blockIdx.x * 2 + r;
    int b = iflat >> 10;

    const float* gp = G + (size_t)iflat * 64 + h * 8;
    float4 gi0 = *(const float4*)gp;
    float4 gi1 = *(const float4*)(gp + 4);
    u64 gp01 = pack2(gi0.x, gi0.y), gp23 = pack2(gi0.z, gi0.w);
    u64 gp45 = pack2(gi1.x, gi1.y), gp67 = pack2(gi1.z, gi1.w);
    float ci = C[(size_t)iflat * 8 + h];

    u64 aw[4];
#pragma unroll
    for (int k = 0; k < 4; k++)
        aw[k] = pack2(0.4f * LOG2E * __ldg(AW + 2 * k),
                      0.4f * LOG2E * __ldg(AW + 2 * k + 1));
    const u64 amask = 0x7fffffff7fffffffULL;

    float l = 0.f;
    u64 a01 = 0, a23 = 0, a45 = 0, a67 = 0;

    const float4* gbase = (const float4*)(G + (size_t)b * N * 64);
    const float* cbase = C + (size_t)b * N * 8;
    const unsigned* bitsrow = BITS + (size_t)iflat * 32;
    const float* gl = gsh + base * S + h * 12;
    const float* cl = csh + base * 8 + h;

    for (int jt = 0; jt < N; jt += TJ) {
        __syncthreads();
        const float4* src = gbase + (size_t)jt * 16;
        for (int idx = tid; idx < TJ * 16; idx += 256) {
            int j = idx >> 4, qidx = idx & 15;
            int q = ((qidx & 7) << 1) | (qidx >> 3);  // phase = even/odd q
            *(float4*)&gsh[j * S + (q >> 1) * 12 + (q & 1) * 4] = src[(j << 4) | q];
        }
        const float* csrc = cbase + (size_t)jt * 8;
        for (int idx = tid; idx < TJ * 8; idx += 256) csh[idx] = csrc[idx];
        __syncthreads();

        uint4 bw = *(const uint4*)(bitsrow + (jt >> 5));
#pragma unroll
        for (int k = 0; k < 4; k++) {
            // chain A: strip k (j = base+16k); chain B: strip k+4 (j = base+16(k+4))
            const float* grA = gl + k * (16 * S);
            const float* grB = grA + 4 * (16 * S);
            ulonglong2 vA0 = *(const ulonglong2*)grA;
            ulonglong2 vA1 = *(const ulonglong2*)(grA + 4);
            ulonglong2 vB0 = *(const ulonglong2*)grB;
            ulonglong2 vB1 = *(const ulonglong2*)(grB + 4);
            float cjA = cl[k * 128];
            float cjB = cl[(k + 4) * 128];
            unsigned sh = base + ((k & 1) << 4);
            unsigned wvA = (k < 2) ? bw.x : bw.y;
            unsigned wvB = (k < 2) ? bw.z : bw.w;
            unsigned mA = (wvA >> sh) & 1u;
            unsigned mB = (wvB >> sh) & 1u;

            u64 s, dA, dB;
            s = add2(gp01, vA0.x); dA = mul2(aw[0], s & amask);
            s = add2(gp01, vB0.x); dB = mul2(aw[0], s & amask);
            s = add2(gp23, vA0.y); dA = fma2(aw[1], s & amask, dA);
            s = add2(gp23, vB0.y); dB = fma2(aw[1], s & amask, dB);
            s = add2(gp45, vA1.x); dA = fma2(aw[2], s & amask, dA);
            s = add2(gp45, vB1.x); dB = fma2(aw[2], s & amask, dB);
            s = add2(gp67, vA1.y); dA = fma2(aw[3], s & amask, dA);
            s = add2(gp67, vB1.y); dB = fma2(aw[3], s & amask, dB);

            float2 eA = unpack2(dA), eB = unpack2(dB);
            float w0 = mA ? fexp2((eA.x + eA.y) + (ci + cjA)) : 0.f;
            float w1 = mB ? fexp2((eB.x + eB.y) + (ci + cjB)) : 0.f;
            l += w0;
            l += w1;
            u64 wp0 = pack2(w0, w0), wp1 = pack2(w1, w1);
            a01 = fma2(wp0, vA0.x, a01); a01 = fma2(wp1, vB0.x, a01);
            a23 = fma2(wp0, vA0.y, a23); a23 = fma2(wp1, vB0.y, a23);
            a45 = fma2(wp0, vA1.x, a45); a45 = fma2(wp1, vB1.x, a45);
            a67 = fma2(wp0, vA1.y, a67); a67 = fma2(wp1, vB1.y, a67);
        }
    }

    // intra-warp reduce across jg strips (plain sums — max-free softmax)
    float2 f01 = unpack2(a01), f23 = unpack2(a23), f45 = unpack2(a45), f67 = unpack2(a67);
    float acc[8] = {f01.x, f01.y, f23.x, f23.y, f45.x, f45.y, f67.x, f67.y};
#pragma unroll
    for (int off = 8; off < 32; off <<= 1) {
        l += __shfl_xor_sync(0xffffffffu, l, off);
#pragma unroll
        for (int f = 0; f < 8; f++) acc[f] += __shfl_xor_sync(0xffffffffu, acc[f], off);
    }

    // cross-warp reduce across 4 split warps
    if (jg == 0) {
        float* p = psum + (w * 8 + h) * 9;
        p[0] = l;
#pragma unroll
        for (int f = 0; f < 8; f++) p[1 + f] = acc[f];
    }
    __syncthreads();
    if (sp == 0 && jg == 0) {
        float L = 0.f, A[8] = {0, 0, 0, 0, 0, 0, 0, 0};
#pragma unroll
        for (int ss = 0; ss < 4; ss++) {
            const float* p = psum + ((ss * 2 + r) * 8 + h) * 9;
            L += p[0];
#pragma unroll
            for (int f = 0; f < 8; f++) A[f] += p[1 + f];
        }
        float inv = 1.f / L;
        float o[8];
#pragma unroll
        for (int f = 0; f < 8; f++) {
            o[f] = A[f] * inv;
            o[f] = o[f] > 0.f ? o[f] : fexp2(o[f] * LOG2E) - 1.f;  // ELU
        }
        float* op = OUT + (size_t)iflat * 64 + h * 8;
        *(float4*)op = make_float4(o[0], o[1], o[2], o[3]);
        *(float4*)(op + 4) = make_float4(o[4], o[5], o[6], o[7]);
    }
}

// ---------------------------------------------------------------------------
// attn layer 2: H=1, F=8. CTA = 256 thr = 8 warps = 8 rows. Whole g2 batch
// staged once; C separate stride-1. Lane L owns j = L + 32k; fully unrolled.
// ---------------------------------------------------------------------------
__global__ __launch_bounds__(256) void attn2_kernel(
    const float* __restrict__ G, const unsigned* __restrict__ BITS,
    const float* __restrict__ C, const float* __restrict__ AW,
    float* __restrict__ OUT, int N) {
    extern __shared__ float smem[];
    float* gsh = smem;            // N*12
    float* csh = smem + N * 12;   // N

    int tid = threadIdx.x;
    int w = tid >> 5, lane = tid & 31;
    int iflat = blockIdx.x * 8 + w;
    int b = iflat >> 10;

    const float4* gb = (const float4*)(G + (size_t)b * N * 8);
    const float* cb = C + (size_t)b * N;
    {
        int jb = tid & 127, q = tid >> 7;  // phase: same q, consecutive j
#pragma unroll
        for (int it = 0; it < 8; it++) {
            int j = jb + it * 128;
            *(float4*)&gsh[j * 12 + q * 4] = gb[j * 2 + q];
        }
    }
    for (int idx = tid; idx < N; idx += 256) csh[idx] = cb[idx];
    __syncthreads();

    const float* gp = G + (size_t)iflat * 8;
    float4 gi0 = *(const float4*)gp;
    float4 gi1 = *(const float4*)(gp + 4);
    u64 gp01 = pack2(gi0.x, gi0.y), gp23 = pack2(gi0.z, gi0.w);
    u64 gp45 = pack2(gi1.x, gi1.y), gp67 = pack2(gi1.z, gi1.w);
    float ci = C[iflat];

    u64 aw[4];
#pragma unroll
    for (int k = 0; k < 4; k++)
        aw[k] = pack2(0.4f * LOG2E * __ldg(AW + 2 * k),
                      0.4f * LOG2E * __ldg(AW + 2 * k + 1));
    const u64 amask = 0x7fffffff7fffffffULL;

    const uint4* b4 = (const uint4*)(BITS + (size_t)iflat * 32);
    const float* gl = gsh + lane * 12;
    const float* cl = csh + lane;

    float l = 0.f;
    u64 a01 = 0, a23 = 0, a45 = 0, a67 = 0;

#pragma unroll
    for (int kk = 0; kk < 8; kk++) {
        uint4 bw = b4[kk];
#pragma unroll
        for (int k2 = 0; k2 < 4; k2++) {
            const float* gr = gl + (kk * 4 + k2) * (32 * 12);
            ulonglong2 v0 = *(const ulonglong2*)gr;
            ulonglong2 v1 = *(const ulonglong2*)(gr + 4);
            float cj = cl[(kk * 4 + k2) * 32];
            unsigned wv = (k2 == 0) ? bw.x : (k2 == 1) ? bw.y : (k2 == 2) ? bw.z : bw.w;
            unsigned m = (wv >> lane) & 1u;

            u64 s01 = add2(gp01, v0.x), s23 = add2(gp23, v0.y);
            u64 s45 = add2(gp45, v1.x), s67 = add2(gp67, v1.y);
            u64 d = mul2(aw[0], s01 & amask);
            d = fma2(aw[1], s23 & amask, d);
            d = fma2(aw[2], s45 & amask, d);
            d = fma2(aw[3], s67 & amask, d);
            float2 ev = unpack2(d);
            float e = (ev.x + ev.y) + (ci + cj);
            float wgt = m ? fexp2(e) : 0.f;
            l += wgt;
            u64 wp = pack2(wgt, wgt);
            a01 = fma2(wp, v0.x, a01);
            a23 = fma2(wp, v0.y, a23);
            a45 = fma2(wp, v1.x, a45);
            a67 = fma2(wp, v1.y, a67);
        }
    }

    float2 f01 = unpack2(a01), f23 = unpack2(a23), f45 = unpack2(a45), f67 = unpack2(a67);
    float acc[8] = {f01.x, f01.y, f23.x, f23.y, f45.x, f45.y, f67.x, f67.y};
#pragma unroll
    for (int off = 1; off < 32; off <<= 1) {
        l += __shfl_xor_sync(0xffffffffu, l, off);
#pragma unroll
        for (int f = 0; f < 8; f++) acc[f] += __shfl_xor_sync(0xffffffffu, acc[f], off);
    }

    if (lane == 0) {
        float inv = 1.f / l;
        float* op = OUT + (size_t)iflat * 8;
        *(float4*)op = make_float4(acc[0] * inv, acc[1] * inv, acc[2] * inv, acc[3] * inv);
        *(float4*)(op + 4) = make_float4(acc[4] * inv, acc[5] * inv, acc[6] * inv, acc[7] * inv);
    }
}

// ---------------------------------------------------------------------------

extern "C" void kernel_launch(void* const* d_in, const int* in_sizes, int n_in,
                              void* d_out, int out_size) {
    const float* x = (const float*)d_in[0];
    const int* adj = (const int*)d_in[1];
    const float* W1 = (const float*)d_in[2];
    const float* a1 = (const float*)d_in[3];
    const float* W2 = (const float*)d_in[4];
    const float* a2 = (const float*)d_in[5];
    float* out = (float*)d_out;

    const int B = 2, N = 1024, M = B * N;

    float *g1, *h1, *g2, *c1, *c2;
    unsigned* bits;
    cudaGetSymbolAddress((void**)&g1, d_g1);
    cudaGetSymbolAddress((void**)&h1, d_h1);
    cudaGetSymbolAddress((void**)&g2, d_g2);
    cudaGetSymbolAddress((void**)&c1, d_c1);
    cudaGetSymbolAddress((void**)&c2, d_c2);
    cudaGetSymbolAddress((void**)&bits, d_bits);

    const int SMEM1 = (128 * 96 + 128 * 8 + 8 * 8 * 9) * 4;  // 55552
    const int SMEM2 = (N * 12 + N) * 4;                       // 53248
    cudaFuncSetAttribute((const void*)attn1_kernel,
                         cudaFuncAttributeMaxDynamicSharedMemorySize, SMEM1);
    cudaFuncSetAttribute((const void*)attn2_kernel,
                         cudaFuncAttributeMaxDynamicSharedMemorySize, SMEM2);

    adj2bits<<<1024, 256>>>(adj, bits);
    gemm_nt<128, 64, 4><<<M / 4, 256>>>(x, W1, a1, g1, c1, M);
    attn1_kernel<<<M / 2, 256, SMEM1>>>(g1, bits, c1, a1, h1, N);
    gemm_nt<64, 8, 32><<<M / 32, 256>>>(h1, W2, a2, g2, c2, M);
    attn2_kernel<<<M / 8, 256, SMEM2>>>(g2, bits, c2, a2, out, N);
}

// round 9
// speedup vs baseline: 1.2677x; 1.2677x over previous
#include <cuda_runtime.h>
#include <cstdint>

// GATv2 2-layer forward.
// x[2,1024,128], adj[2,1024,1024] i32, W1[64,128], a1[8], W2[8,64], a2[8]
// out[2,1024,8] f32
//
// Score identity: leaky(s) = 0.6*s + 0.4*|s|, and softmax is invariant to the
// per-i constant, so:
//   log2e*e'(i,j,h) = C[j,h] + sum_f (0.4*log2e*a_f)*|g_i,f + g_j,f|
// with C = 0.6*log2e*(a . g) computed in the GEMM epilogue (8-lane shfl).
// Max-free softmax (scores O(1); partials sum linearly).
// Adjacency packed to bitmask once (ballot).

#define LOG2E 1.4426950408889634f
typedef unsigned long long u64;
typedef unsigned int u32;

__device__ __forceinline__ float fexp2(float x) {
    float y;
    asm("ex2.approx.ftz.f32 %0, %1;" : "=f"(y) : "f"(x));
    return y;
}
__device__ __forceinline__ u64 add2(u64 a, u64 b) {
    u64 o; asm("add.rn.f32x2 %0,%1,%2;" : "=l"(o) : "l"(a), "l"(b)); return o;
}
__device__ __forceinline__ u64 mul2(u64 a, u64 b) {
    u64 o; asm("mul.rn.f32x2 %0,%1,%2;" : "=l"(o) : "l"(a), "l"(b)); return o;
}
__device__ __forceinline__ u64 fma2(u64 a, u64 b, u64 c) {
    u64 o; asm("fma.rn.f32x2 %0,%1,%2,%3;" : "=l"(o) : "l"(a), "l"(b), "l"(c)); return o;
}
__device__ __forceinline__ u64 pack2(float lo, float hi) {
    u64 o; asm("mov.b64 %0,{%1,%2};" : "=l"(o) : "f"(lo), "f"(hi)); return o;
}
__device__ __forceinline__ float2 unpack2(u64 a) {
    float2 r; asm("mov.b64 {%0,%1},%2;" : "=f"(r.x), "=f"(r.y) : "l"(a)); return r;
}
__device__ __forceinline__ u32 smem_u32(const void* p) {
    return (u32)__cvta_generic_to_shared(p);
}
__device__ __forceinline__ void cpasync16(u32 dst, const void* src) {
    asm volatile("cp.async.cg.shared.global [%0], [%1], 16;" :: "r"(dst), "l"(src));
}
__device__ __forceinline__ void cp_commit() { asm volatile("cp.async.commit_group;"); }
__device__ __forceinline__ void cp_wait1() { asm volatile("cp.async.wait_group 1;"); }

// scratch (allocation-free rule: __device__ globals)
__device__ float d_g1[2 * 1024 * 64];
__device__ float d_h1[2 * 1024 * 64];
__device__ float d_g2[2 * 1024 * 8];
__device__ float d_c1[2 * 1024 * 8];
__device__ float d_c2[2 * 1024];
__device__ unsigned d_bits[2 * 1024 * 32];

// ---------------------------------------------------------------------------
__global__ __launch_bounds__(256) void adj2bits(const int* __restrict__ adj,
                                                unsigned* __restrict__ bits) {
    int gw = (blockIdx.x * 256 + threadIdx.x) >> 5;
    int lane = threadIdx.x & 31;
    int v[8];
    size_t base = (size_t)gw * 8 * 32 + lane;
#pragma unroll
    for (int k = 0; k < 8; k++) v[k] = adj[base + k * 32];
#pragma unroll
    for (int k = 0; k < 8; k++) {
        unsigned m = __ballot_sync(0xffffffffu, v[k] != 0);
        if (lane == 0) bits[gw * 8 + k] = m;
    }
}

// ---------------------------------------------------------------------------
// small GEMM: out[M,K] = X[M,D] @ W[K,D]^T, fused C epilogue:
// C[r, c>>3] = 0.6*log2e * sum_f A[f] * out[r, (c&~7)+f]  (8-lane shfl reduce).
// ---------------------------------------------------------------------------
template <int D, int K, int RPB>
__global__ __launch_bounds__(K* RPB) void gemm_nt(const float* __restrict__ X,
                                                  const float* __restrict__ W,
                                                  const float* __restrict__ A,
                                                  float* __restrict__ out,
                                                  float* __restrict__ C, int M) {
    __shared__ float wsh[D * (K + 1)];
    for (int idx = threadIdx.x; idx < D * K; idx += blockDim.x) {
        int c = idx / D, d = idx % D;
        wsh[d * (K + 1) + c] = W[idx];
    }
    __syncthreads();
    int c = threadIdx.x % K;
    int r = blockIdx.x * RPB + threadIdx.x / K;
    const float4* x4 = (const float4*)(X + (size_t)r * D);
    float acc = 0.f;
#pragma unroll
    for (int d4 = 0; d4 < D / 4; d4++) {
        float4 xv = __ldg(x4 + d4);
        acc = fmaf(xv.x, wsh[(d4 * 4 + 0) * (K + 1) + c], acc);
        acc = fmaf(xv.y, wsh[(d4 * 4 + 1) * (K + 1) + c], acc);
        acc = fmaf(xv.z, wsh[(d4 * 4 + 2) * (K + 1) + c], acc);
        acc = fmaf(xv.w, wsh[(d4 * 4 + 3) * (K + 1) + c], acc);
    }
    out[(size_t)r * K + c] = acc;
    float t = acc * __ldg(A + (c & 7));
    t += __shfl_xor_sync(0xffffffffu, t, 1);
    t += __shfl_xor_sync(0xffffffffu, t, 2);
    t += __shfl_xor_sync(0xffffffffu, t, 4);
    if ((c & 7) == 0) C[(size_t)r * (K / 8) + (c >> 3)] = 0.6f * LOG2E * t;
}

// ---------------------------------------------------------------------------
// attn layer 1: H=8, F=8. CTA = 512 thr = 16 warps = 4 rows x 4 j-splits
// (same shape as the best-measured config). TJ=64 tiles, cp.async double-
// buffered: prefetch tile t+1 while computing tile t.
// lane = jg*8 + h. g tile stride 12/head (conflict-free LDS.128); C separate,
// stride 8 (conflict-free LDS.32). Staging q-permuted.
// ---------------------------------------------------------------------------
__global__ __launch_bounds__(512, 2) void attn1_kernel(
    const float* __restrict__ G, const unsigned* __restrict__ BITS,
    const float* __restrict__ C, const float* __restrict__ AW,
    float* __restrict__ OUT, int N) {
    constexpr int S = 96;   // 8 heads * 12-word stride
    constexpr int TJ = 64;
    constexpr int NT = 16;  // N/TJ tiles

    extern __shared__ float smem[];
    float* gbuf[2] = {smem, smem + TJ * S};
    float* cbuf[2] = {smem + 2 * TJ * S, smem + 2 * TJ * S + TJ * 8};
    float* psum = smem + 2 * TJ * S + 2 * TJ * 8;  // 16 warps * 8 h * 9

    int tid = threadIdx.x;
    int w = tid >> 5, lane = tid & 31;
    int r = w & 3, sp = w >> 2;
    int h = lane & 7, jg = lane >> 3;
    int base = sp * 4 + jg;            // [0,16)

    int iflat = blockIdx.x * 4 + r;
    int b = iflat >> 10;

    const float* gp = G + (size_t)iflat * 64 + h * 8;
    float4 gi0 = *(const float4*)gp;
    float4 gi1 = *(const float4*)(gp + 4);
    u64 gp01 = pack2(gi0.x, gi0.y), gp23 = pack2(gi0.z, gi0.w);
    u64 gp45 = pack2(gi1.x, gi1.y), gp67 = pack2(gi1.z, gi1.w);

    u64 aw[4];
#pragma unroll
    for (int k = 0; k < 4; k++)
        aw[k] = pack2(0.4f * LOG2E * __ldg(AW + 2 * k),
                      0.4f * LOG2E * __ldg(AW + 2 * k + 1));
    const u64 amask = 0x7fffffff7fffffffULL;

    float l = 0.f;
    u64 a01 = 0, a23 = 0, a45 = 0, a67 = 0;

    const float4* gbase = (const float4*)(G + (size_t)b * N * 64);
    const float* cbase = C + (size_t)b * N * 8;
    const unsigned* bitsrow = BITS + (size_t)iflat * 32;

    // staging indices for this thread (2 granules of g, maybe 1 of c)
    int sj0 = tid >> 4, sq0p = tid & 15;
    int sq0 = ((sq0p & 7) << 1) | (sq0p >> 3);
    int sj1 = (tid + 512) >> 4, sq1p = (tid + 512) & 15;
    int sq1 = ((sq1p & 7) << 1) | (sq1p >> 3);

    // prefetch tile 0
    {
        const float4* src = gbase;
        cpasync16(smem_u32(&gbuf[0][sj0 * S + (sq0 >> 1) * 12 + (sq0 & 1) * 4]),
                  src + ((sj0 << 4) | sq0));
        cpasync16(smem_u32(&gbuf[0][sj1 * S + (sq1 >> 1) * 12 + (sq1 & 1) * 4]),
                  src + ((sj1 << 4) | sq1));
        if (tid < 128)
            cpasync16(smem_u32(&cbuf[0][tid * 4]), cbase + tid * 4);
    }
    cp_commit();

    for (int t = 0; t < NT; t++) {
        if (t + 1 < NT) {  // prefetch next tile into the other buffer
            int nb = (t + 1) & 1;
            const float4* src = gbase + (size_t)(t + 1) * TJ * 16;
            cpasync16(smem_u32(&gbuf[nb][sj0 * S + (sq0 >> 1) * 12 + (sq0 & 1) * 4]),
                      src + ((sj0 << 4) | sq0));
            cpasync16(smem_u32(&gbuf[nb][sj1 * S + (sq1 >> 1) * 12 + (sq1 & 1) * 4]),
                      src + ((sj1 << 4) | sq1));
            if (tid < 128)
                cpasync16(smem_u32(&cbuf[nb][tid * 4]),
                          cbase + (size_t)(t + 1) * TJ * 8 + tid * 4);
        }
        cp_commit();
        cp_wait1();          // tile t's group complete (pending <= next tile)
        __syncthreads();

        const float* gl = gbuf[t & 1] + base * S + h * 12;
        const float* cl = cbuf[t & 1] + base * 8 + h;
        uint2 bw = *(const uint2*)(bitsrow + (t << 1));
#pragma unroll
        for (int k = 0; k < 4; k++) {
            const float* gr = gl + k * (16 * S);
            ulonglong2 v0 = *(const ulonglong2*)gr;
            ulonglong2 v1 = *(const ulonglong2*)(gr + 4);
            float cj = cl[k * 128];
            unsigned wv = (k < 2) ? bw.x : bw.y;
            unsigned m = (wv >> (base + ((k & 1) << 4))) & 1u;

            u64 s01 = add2(gp01, v0.x), s23 = add2(gp23, v0.y);
            u64 s45 = add2(gp45, v1.x), s67 = add2(gp67, v1.y);
            u64 d = mul2(aw[0], s01 & amask);
            d = fma2(aw[1], s23 & amask, d);
            d = fma2(aw[2], s45 & amask, d);
            d = fma2(aw[3], s67 & amask, d);
            float2 ev = unpack2(d);
            float e = (ev.x + ev.y) + cj;       // C_i dropped (softmax-invariant)
            float wgt = m ? fexp2(e) : 0.f;
            l += wgt;
            u64 wp = pack2(wgt, wgt);
            a01 = fma2(wp, v0.x, a01);
            a23 = fma2(wp, v0.y, a23);
            a45 = fma2(wp, v1.x, a45);
            a67 = fma2(wp, v1.y, a67);
        }
        __syncthreads();     // everyone done reading buf[t&1] before t+2 overwrite
    }

    // intra-warp reduce across jg strips (plain sums — max-free softmax)
    float2 f01 = unpack2(a01), f23 = unpack2(a23), f45 = unpack2(a45), f67 = unpack2(a67);
    float acc[8] = {f01.x, f01.y, f23.x, f23.y, f45.x, f45.y, f67.x, f67.y};
#pragma unroll
    for (int off = 8; off < 32; off <<= 1) {
        l += __shfl_xor_sync(0xffffffffu, l, off);
#pragma unroll
        for (int f = 0; f < 8; f++) acc[f] += __shfl_xor_sync(0xffffffffu, acc[f], off);
    }

    // cross-warp reduce across 4 split warps
    if (jg == 0) {
        float* p = psum + (w * 8 + h) * 9;
        p[0] = l;
#pragma unroll
        for (int f = 0; f < 8; f++) p[1 + f] = acc[f];
    }
    __syncthreads();
    if (sp == 0 && jg == 0) {
        float L = 0.f, A[8] = {0, 0, 0, 0, 0, 0, 0, 0};
#pragma unroll
        for (int ss = 0; ss < 4; ss++) {
            const float* p = psum + ((ss * 4 + r) * 8 + h) * 9;
            L += p[0];
#pragma unroll
            for (int f = 0; f < 8; f++) A[f] += p[1 + f];
        }
        float inv = 1.f / L;
        float o[8];
#pragma unroll
        for (int f = 0; f < 8; f++) {
            o[f] = A[f] * inv;
            o[f] = o[f] > 0.f ? o[f] : fexp2(o[f] * LOG2E) - 1.f;  // ELU
        }
        float* op = OUT + (size_t)iflat * 64 + h * 8;
        *(float4*)op = make_float4(o[0], o[1], o[2], o[3]);
        *(float4*)(op + 4) = make_float4(o[4], o[5], o[6], o[7]);
    }
}

// ---------------------------------------------------------------------------
// attn layer 2: H=1, F=8. CTA = 256 thr = 8 warps = 8 rows. Whole g2 batch
// staged once; C separate stride-1. Lane L owns j = L + 32k; fully unrolled.
// ---------------------------------------------------------------------------
__global__ __launch_bounds__(256) void attn2_kernel(
    const float* __restrict__ G, const unsigned* __restrict__ BITS,
    const float* __restrict__ C, const float* __restrict__ AW,
    float* __restrict__ OUT, int N) {
    extern __shared__ float smem[];
    float* gsh = smem;            // N*12
    float* csh = smem + N * 12;   // N

    int tid = threadIdx.x;
    int w = tid >> 5, lane = tid & 31;
    int iflat = blockIdx.x * 8 + w;
    int b = iflat >> 10;

    const float4* gb = (const float4*)(G + (size_t)b * N * 8);
    const float* cb = C + (size_t)b * N;
    {
        int jb = tid & 127, q = tid >> 7;  // phase: same q, consecutive j
#pragma unroll
        for (int it = 0; it < 8; it++) {
            int j = jb + it * 128;
            *(float4*)&gsh[j * 12 + q * 4] = gb[j * 2 + q];
        }
    }
    for (int idx = tid; idx < N; idx += 256) csh[idx] = cb[idx];
    __syncthreads();

    const float* gp = G + (size_t)iflat * 8;
    float4 gi0 = *(const float4*)gp;
    float4 gi1 = *(const float4*)(gp + 4);
    u64 gp01 = pack2(gi0.x, gi0.y), gp23 = pack2(gi0.z, gi0.w);
    u64 gp45 = pack2(gi1.x, gi1.y), gp67 = pack2(gi1.z, gi1.w);

    u64 aw[4];
#pragma unroll
    for (int k = 0; k < 4; k++)
        aw[k] = pack2(0.4f * LOG2E * __ldg(AW + 2 * k),
                      0.4f * LOG2E * __ldg(AW + 2 * k + 1));
    const u64 amask = 0x7fffffff7fffffffULL;

    const uint4* b4 = (const uint4*)(BITS + (size_t)iflat * 32);
    const float* gl = gsh + lane * 12;
    const float* cl = csh + lane;

    float l = 0.f;
    u64 a01 = 0, a23 = 0, a45 = 0, a67 = 0;

#pragma unroll
    for (int kk = 0; kk < 8; kk++) {
        uint4 bw = b4[kk];
#pragma unroll
        for (int k2 = 0; k2 < 4; k2++) {
            const float* gr = gl + (kk * 4 + k2) * (32 * 12);
            ulonglong2 v0 = *(const ulonglong2*)gr;
            ulonglong2 v1 = *(const ulonglong2*)(gr + 4);
            float cj = cl[(kk * 4 + k2) * 32];
            unsigned wv = (k2 == 0) ? bw.x : (k2 == 1) ? bw.y : (k2 == 2) ? bw.z : bw.w;
            unsigned m = (wv >> lane) & 1u;

            u64 s01 = add2(gp01, v0.x), s23 = add2(gp23, v0.y);
            u64 s45 = add2(gp45, v1.x), s67 = add2(gp67, v1.y);
            u64 d = mul2(aw[0], s01 & amask);
            d = fma2(aw[1], s23 & amask, d);
            d = fma2(aw[2], s45 & amask, d);
            d = fma2(aw[3], s67 & amask, d);
            float2 ev = unpack2(d);
            float e = (ev.x + ev.y) + cj;       // C_i dropped
            float wgt = m ? fexp2(e) : 0.f;
            l += wgt;
            u64 wp = pack2(wgt, wgt);
            a01 = fma2(wp, v0.x, a01);
            a23 = fma2(wp, v0.y, a23);
            a45 = fma2(wp, v1.x, a45);
            a67 = fma2(wp, v1.y, a67);
        }
    }

    float2 f01 = unpack2(a01), f23 = unpack2(a23), f45 = unpack2(a45), f67 = unpack2(a67);
    float acc[8] = {f01.x, f01.y, f23.x, f23.y, f45.x, f45.y, f67.x, f67.y};
#pragma unroll
    for (int off = 1; off < 32; off <<= 1) {
        l += __shfl_xor_sync(0xffffffffu, l, off);
#pragma unroll
        for (int f = 0; f < 8; f++) acc[f] += __shfl_xor_sync(0xffffffffu, acc[f], off);
    }

    if (lane == 0) {
        float inv = 1.f / l;
        float* op = OUT + (size_t)iflat * 8;
        *(float4*)op = make_float4(acc[0] * inv, acc[1] * inv, acc[2] * inv, acc[3] * inv);
        *(float4*)(op + 4) = make_float4(acc[4] * inv, acc[5] * inv, acc[6] * inv, acc[7] * inv);
    }
}

// ---------------------------------------------------------------------------

extern "C" void kernel_launch(void* const* d_in, const int* in_sizes, int n_in,
                              void* d_out, int out_size) {
    const float* x = (const float*)d_in[0];
    const int* adj = (const int*)d_in[1];
    const float* W1 = (const float*)d_in[2];
    const float* a1 = (const float*)d_in[3];
    const float* W2 = (const float*)d_in[4];
    const float* a2 = (const float*)d_in[5];
    float* out = (float*)d_out;

    const int B = 2, N = 1024, M = B * N;

    float *g1, *h1, *g2, *c1, *c2;
    unsigned* bits;
    cudaGetSymbolAddress((void**)&g1, d_g1);
    cudaGetSymbolAddress((void**)&h1, d_h1);
    cudaGetSymbolAddress((void**)&g2, d_g2);
    cudaGetSymbolAddress((void**)&c1, d_c1);
    cudaGetSymbolAddress((void**)&c2, d_c2);
    cudaGetSymbolAddress((void**)&bits, d_bits);

    // smem: 2 g bufs + 2 c bufs + psum
    const int SMEM1 = (2 * 64 * 96 + 2 * 64 * 8 + 16 * 8 * 9) * 4;  // 57856
    const int SMEM2 = (N * 12 + N) * 4;                              // 53248
    cudaFuncSetAttribute((const void*)attn1_kernel,
                         cudaFuncAttributeMaxDynamicSharedMemorySize, SMEM1);
    cudaFuncSetAttribute((const void*)attn2_kernel,
                         cudaFuncAttributeMaxDynamicSharedMemorySize, SMEM2);

    adj2bits<<<1024, 256>>>(adj, bits);
    gemm_nt<128, 64, 4><<<M / 4, 256>>>(x, W1, a1, g1, c1, M);
    attn1_kernel<<<M / 4, 512, SMEM1>>>(g1, bits, c1, a1, h1, N);
    gemm_nt<64, 8, 8><<<M / 8, 64>>>(h1, W2, a2, g2, c2, M);
    attn2_kernel<<<M / 8, 256, SMEM2>>>(g2, bits, c2, a2, out, N);
}

// round 10
// speedup vs baseline: 1.4039x; 1.1074x over previous
#include <cuda_runtime.h>
#include <cstdint>

// GATv2 2-layer forward.
// x[2,1024,128], adj[2,1024,1024] i32, W1[64,128], a1[8], W2[8,64], a2[8]
// out[2,1024,8] f32
//
// Score identity: leaky(s) = 0.6*s + 0.4*|s|; softmax is invariant to the
// per-i constant, so:
//   log2e*e'(i,j,h) = C[j,h] + sum_f (0.4*log2e*a_f)*|g_i,f + g_j,f|
// with C = 0.6*log2e*(a . g) computed in the GEMM epilogues.
// Max-free softmax (scores O(1); partials sum linearly).
// Adjacency packed to bitmask once (ballot), fused with gemm1's launch.
// 4 launches total: [adj2bits||gemm1+C] -> attn1 -> gemm2+C -> attn2.

#define LOG2E 1.4426950408889634f
typedef unsigned long long u64;
typedef unsigned int u32;

__device__ __forceinline__ float fexp2(float x) {
    float y;
    asm("ex2.approx.ftz.f32 %0, %1;" : "=f"(y) : "f"(x));
    return y;
}
__device__ __forceinline__ u64 add2(u64 a, u64 b) {
    u64 o; asm("add.rn.f32x2 %0,%1,%2;" : "=l"(o) : "l"(a), "l"(b)); return o;
}
__device__ __forceinline__ u64 mul2(u64 a, u64 b) {
    u64 o; asm("mul.rn.f32x2 %0,%1,%2;" : "=l"(o) : "l"(a), "l"(b)); return o;
}
__device__ __forceinline__ u64 fma2(u64 a, u64 b, u64 c) {
    u64 o; asm("fma.rn.f32x2 %0,%1,%2,%3;" : "=l"(o) : "l"(a), "l"(b), "l"(c)); return o;
}
__device__ __forceinline__ u64 pack2(float lo, float hi) {
    u64 o; asm("mov.b64 %0,{%1,%2};" : "=l"(o) : "f"(lo), "f"(hi)); return o;
}
__device__ __forceinline__ float2 unpack2(u64 a) {
    float2 r; asm("mov.b64 {%0,%1},%2;" : "=f"(r.x), "=f"(r.y) : "l"(a)); return r;
}

// scratch (allocation-free rule: __device__ globals)
__device__ float d_g1[2 * 1024 * 64];
__device__ float d_h1[2 * 1024 * 64];
__device__ float d_g2[2 * 1024 * 8];
__device__ float d_c1[2 * 1024 * 8];
__device__ float d_c2[2 * 1024];
__device__ unsigned d_bits[2 * 1024 * 32];

// ---------------------------------------------------------------------------
// Fused pre-pass. Blocks [0,1024): adjacency->bitmask. Blocks [1024,1536):
// gemm1 out[M,64] = X[M,128] @ W[64,128]^T with fused C epilogue
// (C[r,h] = 0.6*log2e * sum_f A[f]*out[r,h*8+f], 8-lane shfl reduce).
// ---------------------------------------------------------------------------
__global__ __launch_bounds__(256) void fused_pre(
    const int* __restrict__ adj, unsigned* __restrict__ bits,
    const float* __restrict__ X, const float* __restrict__ W,
    const float* __restrict__ A, float* __restrict__ g1,
    float* __restrict__ C) {
    constexpr int D = 128, K = 64, RPB = 4;
    __shared__ float wsh[D * (K + 1)];
    int tid = threadIdx.x;

    if (blockIdx.x < 1024) {  // ---- adj2bits ----
        int gw = (blockIdx.x * 256 + tid) >> 5;
        int lane = tid & 31;
        int v[8];
        size_t base = (size_t)gw * 8 * 32 + lane;
#pragma unroll
        for (int k = 0; k < 8; k++) v[k] = adj[base + k * 32];
#pragma unroll
        for (int k = 0; k < 8; k++) {
            unsigned m = __ballot_sync(0xffffffffu, v[k] != 0);
            if (lane == 0) bits[gw * 8 + k] = m;
        }
        return;
    }
    // ---- gemm1 + C ----
    int bid = blockIdx.x - 1024;
    for (int idx = tid; idx < D * K; idx += 256) {
        int c = idx / D, d = idx % D;
        wsh[d * (K + 1) + c] = W[idx];
    }
    __syncthreads();
    int c = tid % K;
    int r = bid * RPB + tid / K;
    const float4* x4 = (const float4*)(X + (size_t)r * D);
    float acc = 0.f;
#pragma unroll
    for (int d4 = 0; d4 < D / 4; d4++) {
        float4 xv = __ldg(x4 + d4);
        acc = fmaf(xv.x, wsh[(d4 * 4 + 0) * (K + 1) + c], acc);
        acc = fmaf(xv.y, wsh[(d4 * 4 + 1) * (K + 1) + c], acc);
        acc = fmaf(xv.z, wsh[(d4 * 4 + 2) * (K + 1) + c], acc);
        acc = fmaf(xv.w, wsh[(d4 * 4 + 3) * (K + 1) + c], acc);
    }
    g1[(size_t)r * K + c] = acc;
    float t = acc * __ldg(A + (c & 7));
    t += __shfl_xor_sync(0xffffffffu, t, 1);
    t += __shfl_xor_sync(0xffffffffu, t, 2);
    t += __shfl_xor_sync(0xffffffffu, t, 4);
    if ((c & 7) == 0) C[(size_t)r * (K / 8) + (c >> 3)] = 0.6f * LOG2E * t;
}

// ---------------------------------------------------------------------------
// gemm2: warp-per-row. out[M,8] = X[M,64] @ W[8,64]^T, fused C epilogue.
// Lane l holds x[2l..2l+1]; 8 partials; 5-round butterfly reduce.
// ---------------------------------------------------------------------------
__global__ __launch_bounds__(256) void gemm2_kernel(
    const float* __restrict__ X, const float* __restrict__ W,
    const float* __restrict__ A, float* __restrict__ out,
    float* __restrict__ C, int M) {
    __shared__ float wsh[8 * 64];
    int tid = threadIdx.x;
    for (int i = tid; i < 512; i += 256) wsh[i] = W[i];
    __syncthreads();
    int w = tid >> 5, lane = tid & 31;
    int r = blockIdx.x * 8 + w;
    float2 x = *(const float2*)(X + (size_t)r * 64 + lane * 2);
    float p[8];
#pragma unroll
    for (int k = 0; k < 8; k++) {
        float2 wv = *(const float2*)&wsh[k * 64 + lane * 2];
        p[k] = x.x * wv.x + x.y * wv.y;
    }
#pragma unroll
    for (int off = 16; off >= 1; off >>= 1) {
#pragma unroll
        for (int k = 0; k < 8; k++) p[k] += __shfl_xor_sync(0xffffffffu, p[k], off);
    }
    if (lane == 0) {
        float cacc = 0.f;
#pragma unroll
        for (int k = 0; k < 8; k++) {
            out[(size_t)r * 8 + k] = p[k];
            cacc = fmaf(p[k], __ldg(A + k), cacc);
        }
        C[r] = 0.6f * LOG2E * cacc;
    }
}

// ---------------------------------------------------------------------------
// attn layer 1: H=8, F=8. CTA = 512 thr = 16 warps = 4 rows x 4 j-splits
// (best-measured R5 shape). TJ=128 tiles, LDG->STS staging, 2 barriers/tile.
// lane = jg*8 + h. g tile stride 12/head (conflict-free LDS.128); C separate,
// stride 8 (conflict-free LDS.32). Staging q-permuted (conflict-free STS.128).
// ---------------------------------------------------------------------------
__global__ __launch_bounds__(512, 2) void attn1_kernel(
    const float* __restrict__ G, const unsigned* __restrict__ BITS,
    const float* __restrict__ C, const float* __restrict__ AW,
    float* __restrict__ OUT, int N) {
    constexpr int S = 96;   // 8 heads * 12-word stride
    constexpr int TJ = 128;

    extern __shared__ float smem[];
    float* gsh = smem;                 // TJ*S
    float* csh = smem + TJ * S;        // TJ*8
    float* psum = csh + TJ * 8;        // 16*8*9

    int tid = threadIdx.x;
    int w = tid >> 5, lane = tid & 31;
    int r = w & 3, sp = w >> 2;
    int h = lane & 7, jg = lane >> 3;
    int base = sp * 4 + jg;            // [0,16)

    int iflat = blockIdx.x * 4 + r;
    int b = iflat >> 10;

    const float* gp = G + (size_t)iflat * 64 + h * 8;
    float4 gi0 = *(const float4*)gp;
    float4 gi1 = *(const float4*)(gp + 4);
    u64 gp01 = pack2(gi0.x, gi0.y), gp23 = pack2(gi0.z, gi0.w);
    u64 gp45 = pack2(gi1.x, gi1.y), gp67 = pack2(gi1.z, gi1.w);

    u64 aw[4];
#pragma unroll
    for (int k = 0; k < 4; k++)
        aw[k] = pack2(0.4f * LOG2E * __ldg(AW + 2 * k),
                      0.4f * LOG2E * __ldg(AW + 2 * k + 1));
    const u64 amask = 0x7fffffff7fffffffULL;

    float l = 0.f;
    u64 a01 = 0, a23 = 0, a45 = 0, a67 = 0;

    const float4* gbase = (const float4*)(G + (size_t)b * N * 64);
    const float* cbase = C + (size_t)b * N * 8;
    const unsigned* bitsrow = BITS + (size_t)iflat * 32;
    const float* gl = gsh + base * S + h * 12;
    const float* cl = csh + base * 8 + h;

    for (int jt = 0; jt < N; jt += TJ) {
        __syncthreads();
        const float4* src = gbase + (size_t)jt * 16;
        for (int idx = tid; idx < TJ * 16; idx += 512) {
            int j = idx >> 4, qidx = idx & 15;
            int q = ((qidx & 7) << 1) | (qidx >> 3);  // phase = even/odd q
            *(float4*)&gsh[j * S + (q >> 1) * 12 + (q & 1) * 4] = src[(j << 4) | q];
        }
        const float* csrc = cbase + (size_t)jt * 8;
        for (int idx = tid; idx < TJ * 8; idx += 512) csh[idx] = csrc[idx];
        __syncthreads();

        uint4 bw = *(const uint4*)(bitsrow + (jt >> 5));
#pragma unroll
        for (int k = 0; k < 8; k++) {
            const float* gr = gl + k * (16 * S);
            ulonglong2 v0 = *(const ulonglong2*)gr;
            ulonglong2 v1 = *(const ulonglong2*)(gr + 4);
            float cj = cl[k * 128];
            unsigned wv = (k < 2) ? bw.x : (k < 4) ? bw.y : (k < 6) ? bw.z : bw.w;
            unsigned m = (wv >> (base + ((k & 1) << 4))) & 1u;

            u64 s01 = add2(gp01, v0.x), s23 = add2(gp23, v0.y);
            u64 s45 = add2(gp45, v1.x), s67 = add2(gp67, v1.y);
            u64 d = mul2(aw[0], s01 & amask);
            d = fma2(aw[1], s23 & amask, d);
            d = fma2(aw[2], s45 & amask, d);
            d = fma2(aw[3], s67 & amask, d);
            float2 ev = unpack2(d);
            float e = (ev.x + ev.y) + cj;       // C_i dropped (softmax-invariant)
            float wgt = m ? fexp2(e) : 0.f;
            l += wgt;
            u64 wp = pack2(wgt, wgt);
            a01 = fma2(wp, v0.x, a01);
            a23 = fma2(wp, v0.y, a23);
            a45 = fma2(wp, v1.x, a45);
            a67 = fma2(wp, v1.y, a67);
        }
    }

    // intra-warp reduce across jg strips (plain sums — max-free softmax)
    float2 f01 = unpack2(a01), f23 = unpack2(a23), f45 = unpack2(a45), f67 = unpack2(a67);
    float acc[8] = {f01.x, f01.y, f23.x, f23.y, f45.x, f45.y, f67.x, f67.y};
#pragma unroll
    for (int off = 8; off < 32; off <<= 1) {
        l += __shfl_xor_sync(0xffffffffu, l, off);
#pragma unroll
        for (int f = 0; f < 8; f++) acc[f] += __shfl_xor_sync(0xffffffffu, acc[f], off);
    }

    // cross-warp reduce across 4 split warps
    if (jg == 0) {
        float* p = psum + (w * 8 + h) * 9;
        p[0] = l;
#pragma unroll
        for (int f = 0; f < 8; f++) p[1 + f] = acc[f];
    }
    __syncthreads();
    if (sp == 0 && jg == 0) {
        float L = 0.f, A[8] = {0, 0, 0, 0, 0, 0, 0, 0};
#pragma unroll
        for (int ss = 0; ss < 4; ss++) {
            const float* p = psum + ((ss * 4 + r) * 8 + h) * 9;
            L += p[0];
#pragma unroll
            for (int f = 0; f < 8; f++) A[f] += p[1 + f];
        }
        float inv = 1.f / L;
        float o[8];
#pragma unroll
        for (int f = 0; f < 8; f++) {
            o[f] = A[f] * inv;
            o[f] = o[f] > 0.f ? o[f] : fexp2(o[f] * LOG2E) - 1.f;  // ELU
        }
        float* op = OUT + (size_t)iflat * 64 + h * 8;
        *(float4*)op = make_float4(o[0], o[1], o[2], o[3]);
        *(float4*)(op + 4) = make_float4(o[4], o[5], o[6], o[7]);
    }
}

// ---------------------------------------------------------------------------
// attn layer 2: H=1, F=8. CTA = 256 thr = 8 warps = 8 rows. Whole g2 batch
// staged once; C separate stride-1. Lane L owns j = L + 32k; fully unrolled.
// ---------------------------------------------------------------------------
__global__ __launch_bounds__(256) void attn2_kernel(
    const float* __restrict__ G, const unsigned* __restrict__ BITS,
    const float* __restrict__ C, const float* __restrict__ AW,
    float* __restrict__ OUT, int N) {
    extern __shared__ float smem[];
    float* gsh = smem;            // N*12
    float* csh = smem + N * 12;   // N

    int tid = threadIdx.x;
    int w = tid >> 5, lane = tid & 31;
    int iflat = blockIdx.x * 8 + w;
    int b = iflat >> 10;

    const float4* gb = (const float4*)(G + (size_t)b * N * 8);
    const float* cb = C + (size_t)b * N;
    {
        int jb = tid & 127, q = tid >> 7;  // phase: same q, consecutive j
#pragma unroll
        for (int it = 0; it < 8; it++) {
            int j = jb + it * 128;
            *(float4*)&gsh[j * 12 + q * 4] = gb[j * 2 + q];
        }
    }
    for (int idx = tid; idx < N; idx += 256) csh[idx] = cb[idx];
    __syncthreads();

    const float* gp = G + (size_t)iflat * 8;
    float4 gi0 = *(const float4*)gp;
    float4 gi1 = *(const float4*)(gp + 4);
    u64 gp01 = pack2(gi0.x, gi0.y), gp23 = pack2(gi0.z, gi0.w);
    u64 gp45 = pack2(gi1.x, gi1.y), gp67 = pack2(gi1.z, gi1.w);

    u64 aw[4];
#pragma unroll
    for (int k = 0; k < 4; k++)
        aw[k] = pack2(0.4f * LOG2E * __ldg(AW + 2 * k),
                      0.4f * LOG2E * __ldg(AW + 2 * k + 1));
    const u64 amask = 0x7fffffff7fffffffULL;

    const uint4* b4 = (const uint4*)(BITS + (size_t)iflat * 32);
    const float* gl = gsh + lane * 12;
    const float* cl = csh + lane;

    float l = 0.f;
    u64 a01 = 0, a23 = 0, a45 = 0, a67 = 0;

#pragma unroll
    for (int kk = 0; kk < 8; kk++) {
        uint4 bw = b4[kk];
#pragma unroll
        for (int k2 = 0; k2 < 4; k2++) {
            const float* gr = gl + (kk * 4 + k2) * (32 * 12);
            ulonglong2 v0 = *(const ulonglong2*)gr;
            ulonglong2 v1 = *(const ulonglong2*)(gr + 4);
            float cj = cl[(kk * 4 + k2) * 32];
            unsigned wv = (k2 == 0) ? bw.x : (k2 == 1) ? bw.y : (k2 == 2) ? bw.z : bw.w;
            unsigned m = (wv >> lane) & 1u;

            u64 s01 = add2(gp01, v0.x), s23 = add2(gp23, v0.y);
            u64 s45 = add2(gp45, v1.x), s67 = add2(gp67, v1.y);
            u64 d = mul2(aw[0], s01 & amask);
            d = fma2(aw[1], s23 & amask, d);
            d = fma2(aw[2], s45 & amask, d);
            d = fma2(aw[3], s67 & amask, d);
            float2 ev = unpack2(d);
            float e = (ev.x + ev.y) + cj;       // C_i dropped
            float wgt = m ? fexp2(e) : 0.f;
            l += wgt;
            u64 wp = pack2(wgt, wgt);
            a01 = fma2(wp, v0.x, a01);
            a23 = fma2(wp, v0.y, a23);
            a45 = fma2(wp, v1.x, a45);
            a67 = fma2(wp, v1.y, a67);
        }
    }

    float2 f01 = unpack2(a01), f23 = unpack2(a23), f45 = unpack2(a45), f67 = unpack2(a67);
    float acc[8] = {f01.x, f01.y, f23.x, f23.y, f45.x, f45.y, f67.x, f67.y};
#pragma unroll
    for (int off = 1; off < 32; off <<= 1) {
        l += __shfl_xor_sync(0xffffffffu, l, off);
#pragma unroll
        for (int f = 0; f < 8; f++) acc[f] += __shfl_xor_sync(0xffffffffu, acc[f], off);
    }

    if (lane == 0) {
        float inv = 1.f / l;
        float* op = OUT + (size_t)iflat * 8;
        *(float4*)op = make_float4(acc[0] * inv, acc[1] * inv, acc[2] * inv, acc[3] * inv);
        *(float4*)(op + 4) = make_float4(acc[4] * inv, acc[5] * inv, acc[6] * inv, acc[7] * inv);
    }
}

// ---------------------------------------------------------------------------

extern "C" void kernel_launch(void* const* d_in, const int* in_sizes, int n_in,
                              void* d_out, int out_size) {
    const float* x = (const float*)d_in[0];
    const int* adj = (const int*)d_in[1];
    const float* W1 = (const float*)d_in[2];
    const float* a1 = (const float*)d_in[3];
    const float* W2 = (const float*)d_in[4];
    const float* a2 = (const float*)d_in[5];
    float* out = (float*)d_out;

    const int B = 2, N = 1024, M = B * N;

    float *g1, *h1, *g2, *c1, *c2;
    unsigned* bits;
    cudaGetSymbolAddress((void**)&g1, d_g1);
    cudaGetSymbolAddress((void**)&h1, d_h1);
    cudaGetSymbolAddress((void**)&g2, d_g2);
    cudaGetSymbolAddress((void**)&c1, d_c1);
    cudaGetSymbolAddress((void**)&c2, d_c2);
    cudaGetSymbolAddress((void**)&bits, d_bits);

    const int SMEM1 = (128 * 96 + 128 * 8 + 16 * 8 * 9) * 4;  // 57856
    const int SMEM2 = (N * 12 + N) * 4;                        // 53248
    cudaFuncSetAttribute((const void*)attn1_kernel,
                         cudaFuncAttributeMaxDynamicSharedMemorySize, SMEM1);
    cudaFuncSetAttribute((const void*)attn2_kernel,
                         cudaFuncAttributeMaxDynamicSharedMemorySize, SMEM2);

    // K1: adj2bits (blocks 0..1023)  ||  gemm1+C (blocks 1024..1535)
    fused_pre<<<1536, 256>>>(adj, bits, x, W1, a1, g1, c1);
    // K2: attn1 (+ELU)
    attn1_kernel<<<M / 4, 512, SMEM1>>>(g1, bits, c1, a1, h1, N);
    // K3: gemm2+C (warp-per-row)
    gemm2_kernel<<<M / 8, 256>>>(h1, W2, a2, g2, c2, M);
    // K4: attn2
    attn2_kernel<<<M / 8, 256, SMEM2>>>(g2, bits, c2, a2, out, N);
}